// round 1
// baseline (speedup 1.0000x reference)
#include <cuda_runtime.h>
#include <math.h>

#define B_  8
#define CIN 64
#define H_  128
#define W_  128
#define HO  64
#define WO  128
#define CO  64

// Scratch (no allocations allowed -> __device__ globals)
__device__ float g_offmask[B_*27*HO*WO];   // ch 0..17 offsets, 18..26 sigmoid(mask)
__device__ float g_Wom[576*32];            // [c*9+k][o] padded to 32 o's
__device__ float g_bias[32];
__device__ float g_Wt[9*64*64];            // [k][c][o]

// ---------------------------------------------------------------------------
// Kernel 0: weight transpose / repack (coalesced consumers later)
// ---------------------------------------------------------------------------
__global__ void prep_kernel(const float* __restrict__ w_off, const float* __restrict__ b_off,
                            const float* __restrict__ w_mask, const float* __restrict__ b_mask,
                            const float* __restrict__ w_conv) {
    int idx = blockIdx.x * blockDim.x + threadIdx.x;
    if (idx < 9*64*64) {
        int k = idx >> 12; int r = idx & 4095; int c = r >> 6; int o = r & 63;
        g_Wt[idx] = w_conv[(o*64 + c)*9 + k];
    }
    if (idx < 576*32) {
        int ck = idx >> 5; int o = idx & 31;
        int c = ck / 9; int k = ck % 9;
        float v = 0.f;
        if (o < 18)       v = w_off[(o*64 + c)*9 + k];
        else if (o < 27)  v = w_mask[((o-18)*64 + c)*9 + k];
        g_Wom[idx] = v;
    }
    if (idx < 32) {
        float v = 0.f;
        if (idx < 18)      v = b_off[idx];
        else if (idx < 27) v = b_mask[idx - 18];
        g_bias[idx] = v;
    }
}

// ---------------------------------------------------------------------------
// Kernel 1: offset + mask conv (27 out-ch, stride (2,1), pad (1,1))
// Block: (b, ho, 32 wo). Smem: x patch [64][3][34] + weights [576][32].
// Thread: px = tid&31, 4 consecutive out-channels.
// ---------------------------------------------------------------------------
__global__ void __launch_bounds__(256) conv_om_kernel(const float* __restrict__ x) {
    extern __shared__ float smem[];
    float* sp = smem;              // 64*102 = 6528 floats
    float* sw = smem + 6528;       // 576*32 = 18432 floats

    int tid = threadIdx.x;
    int wo0 = blockIdx.x * 32;
    int ho  = blockIdx.y;
    int b   = blockIdx.z;

    // weights -> smem (coalesced float4)
    {
        float4* d4 = (float4*)sw;
        const float4* s4 = (const float4*)g_Wom;
        for (int t = tid; t < 18432/4; t += 256) d4[t] = s4[t];
    }
    // x patch -> smem (rows 2ho-1..2ho+1, cols wo0-1..wo0+32, zero padded)
    const float* xb = x + (size_t)b * CIN * H_ * W_;
    for (int t = tid; t < 64*102; t += 256) {
        int c = t / 102; int r = t % 102; int ky = r / 34; int col = r % 34;
        int gy = 2*ho - 1 + ky;
        int gx = wo0 - 1 + col;
        float v = 0.f;
        if (gy >= 0 && gy < H_ && gx >= 0 && gx < W_)
            v = xb[(c*H_ + gy)*W_ + gx];
        sp[t] = v;
    }
    __syncthreads();

    int px = tid & 31;
    int o0 = (tid >> 5) * 4;
    float acc0 = g_bias[o0+0], acc1 = g_bias[o0+1];
    float acc2 = g_bias[o0+2], acc3 = g_bias[o0+3];

    for (int c = 0; c < 64; ++c) {
        const float* prow = sp + c*102;
        #pragma unroll
        for (int ky = 0; ky < 3; ++ky) {
            #pragma unroll
            for (int kx = 0; kx < 3; ++kx) {
                float pv = prow[ky*34 + px + kx];
                int ck = c*9 + ky*3 + kx;
                float4 w = *(const float4*)&sw[ck*32 + o0];
                acc0 += w.x*pv; acc1 += w.y*pv; acc2 += w.z*pv; acc3 += w.w*pv;
            }
        }
    }

    int wo = wo0 + px;
    float accs[4] = {acc0, acc1, acc2, acc3};
    #pragma unroll
    for (int j = 0; j < 4; ++j) {
        int o = o0 + j;
        if (o < 27) {
            float v = accs[j];
            if (o >= 18) v = 1.f / (1.f + expf(-v));   // sigmoid for mask channels
            g_offmask[((b*27 + o)*HO + ho)*WO + wo] = v;
        }
    }
}

// ---------------------------------------------------------------------------
// Kernel 2: fused bilinear gather + 64x576 GEMM
// Block: (b, ho, 32 wo). Per-k: stage W_k [64c][64o] + sampled S [64c][32px].
// Thread: px = tid&31, 8 consecutive out-channels (tid>>5)*8.
// ---------------------------------------------------------------------------
__global__ void __launch_bounds__(256) deform_kernel(const float* __restrict__ x,
                                                     float* __restrict__ out) {
    __shared__ float sS[64][33];     // sampled, padded rows
    __shared__ float sW[64*64];      // W_k, [c][o]
    __shared__ float s_cw[4][288];   // 4 corner weights (validity & mask folded in)
    __shared__ int   s_iy0[288], s_iy1[288], s_ix0[288], s_ix1[288];

    int tid = threadIdx.x;
    int wo0 = blockIdx.x * 32;
    int ho  = blockIdx.y;
    int b   = blockIdx.z;

    // Precompute all 9x32 bilinear metadata once
    for (int t = tid; t < 288; t += 256) {
        int k = t >> 5; int p = t & 31; int wo = wo0 + p;
        const float* om = g_offmask + (size_t)b*27*HO*WO;
        float offy = om[((2*k)   * HO + ho)*WO + wo];
        float offx = om[((2*k+1) * HO + ho)*WO + wo];
        float m    = om[((18+k)  * HO + ho)*WO + wo];
        float py  = offy + (float)(k/3) + (float)(2*ho - 1);
        float pxx = offx + (float)(k%3) + (float)(wo - 1);
        float y0f = floorf(py),  x0f = floorf(pxx);
        float dy = py - y0f,     dx = pxx - x0f;
        int y0 = (int)y0f, x0i = (int)x0f;
        int y1 = y0 + 1,   x1  = x0i + 1;
        bool vy0 = (y0  >= 0) && (y0  < H_);
        bool vy1 = (y1  >= 0) && (y1  < H_);
        bool vx0 = (x0i >= 0) && (x0i < W_);
        bool vx1 = (x1  >= 0) && (x1  < W_);
        s_cw[0][t] = (1.f-dy)*(1.f-dx)*m * ((vy0 && vx0) ? 1.f : 0.f);
        s_cw[1][t] = (1.f-dy)*dx      *m * ((vy0 && vx1) ? 1.f : 0.f);
        s_cw[2][t] = dy*(1.f-dx)      *m * ((vy1 && vx0) ? 1.f : 0.f);
        s_cw[3][t] = dy*dx            *m * ((vy1 && vx1) ? 1.f : 0.f);
        s_iy0[t] = min(max(y0, 0),  H_-1);
        s_iy1[t] = min(max(y1, 0),  H_-1);
        s_ix0[t] = min(max(x0i, 0), W_-1);
        s_ix1[t] = min(max(x1, 0),  W_-1);
    }

    float acc[8];
    #pragma unroll
    for (int j = 0; j < 8; ++j) acc[j] = 0.f;

    int p   = tid & 31;
    int grp = tid >> 5;
    const float* xb = x + (size_t)b * CIN * H_ * W_;

    #pragma unroll 1
    for (int k = 0; k < 9; ++k) {
        __syncthreads();   // also orders metadata (k==0) and guards smem reuse
        // stage W_k (coalesced)
        {
            float4* d4 = (float4*)sW;
            const float4* s4 = (const float4*)(g_Wt + k*4096);
            for (int t = tid; t < 1024; t += 256) d4[t] = s4[t];
        }
        // gather: 8 channels per thread, 4 corner loads each (near-coalesced over px)
        {
            int mb = (k << 5) + p;
            int iy0 = s_iy0[mb]*W_, iy1 = s_iy1[mb]*W_;
            int ix0 = s_ix0[mb],    ix1 = s_ix1[mb];
            float w00 = s_cw[0][mb], w01 = s_cw[1][mb];
            float w10 = s_cw[2][mb], w11 = s_cw[3][mb];
            #pragma unroll
            for (int i = 0; i < 8; ++i) {
                int c = grp*8 + i;
                const float* xc = xb + c*(H_*W_);
                float v = w00*__ldg(xc + iy0 + ix0)
                        + w01*__ldg(xc + iy0 + ix1)
                        + w10*__ldg(xc + iy1 + ix0)
                        + w11*__ldg(xc + iy1 + ix1);
                sS[c][p] = v;
            }
        }
        __syncthreads();
        // GEMM accumulate: acc[o0..o0+7] += W_k[c][o] * S[c][px]
        int o0 = grp * 8;
        #pragma unroll 16
        for (int c = 0; c < 64; ++c) {
            float sv = sS[c][p];
            float4 wa = *(const float4*)&sW[c*64 + o0];
            float4 wb = *(const float4*)&sW[c*64 + o0 + 4];
            acc[0] += wa.x*sv; acc[1] += wa.y*sv; acc[2] += wa.z*sv; acc[3] += wa.w*sv;
            acc[4] += wb.x*sv; acc[5] += wb.y*sv; acc[6] += wb.z*sv; acc[7] += wb.w*sv;
        }
    }

    int o0 = grp * 8;
    #pragma unroll
    for (int j = 0; j < 8; ++j)
        out[(((size_t)b*CO + o0 + j)*HO + ho)*WO + wo0 + p] = acc[j];
}

// ---------------------------------------------------------------------------
extern "C" void kernel_launch(void* const* d_in, const int* in_sizes, int n_in,
                              void* d_out, int out_size) {
    const float* x      = (const float*)d_in[0];
    const float* w_off  = (const float*)d_in[1];
    const float* b_off  = (const float*)d_in[2];
    const float* w_mask = (const float*)d_in[3];
    const float* b_mask = (const float*)d_in[4];
    const float* w_conv = (const float*)d_in[5];
    float* out = (float*)d_out;

    prep_kernel<<<144, 256>>>(w_off, b_off, w_mask, b_mask, w_conv);

    int smem1 = (6528 + 18432) * (int)sizeof(float);   // 99,840 B
    cudaFuncSetAttribute((const void*)conv_om_kernel,
                         cudaFuncAttributeMaxDynamicSharedMemorySize, smem1);
    conv_om_kernel<<<dim3(4, 64, 8), 256, smem1>>>(x);

    deform_kernel<<<dim3(4, 64, 8), 256>>>(x, out);
}